// round 8
// baseline (speedup 1.0000x reference)
#include <cuda_runtime.h>
#include <cuda_bf16.h>
#include <cstdint>
#include <cstddef>

#define NN 50000
#define NE 800000
#define HID 256

// smem stage layout (bytes, pitch 80/row of 32 bf16 + pad):
// Ah[128x80]=10240 | Al=10240 | Bh[128x80]=10240 | Bl=10240
#define STAGE_B 40960

// ---------------- scratch (device globals: no allocation allowed) ----------------
__device__ __nv_bfloat16 g_ah[(size_t)NN * HID], g_al[(size_t)NN * HID];
__device__ __nv_bfloat16 g_th[(size_t)NN * HID], g_tl[(size_t)NN * HID];
__device__ __nv_bfloat16 g_gh[(size_t)NN * HID], g_gl[(size_t)NN * HID];
__device__ __nv_bfloat16 g_uh[(size_t)NN * HID], g_ul[(size_t)NN * HID];
__device__ int g_cnt[NN];
__device__ int g_rowptr[NN + 1];
__device__ int g_fill[NN];
__device__ int g_col[NE];
__device__ float g_cbt[256];         // b2@Wc + conv_b
__device__ float g_cbu[256];         // b2@P1 + post_b1
__device__ __nv_bfloat16 g_wth[256 * 256], g_wtl[256 * 256];   // t-GEMM weights
__device__ __nv_bfloat16 g_wuh[256 * 512], g_wul[256 * 512];   // u-GEMM weights

// ---------------- helpers ----------------
__device__ __forceinline__ uint32_t s2u(const void* p) {
    uint32_t a;
    asm("{ .reg .u64 t; cvta.to.shared.u64 t, %1; cvt.u32.u64 %0, t; }" : "=r"(a) : "l"(p));
    return a;
}
__device__ __forceinline__ void cp16(uint32_t dst, const void* src, int srcsz) {
    asm volatile("cp.async.cg.shared.global [%0], [%1], 16, %2;"
                 :: "r"(dst), "l"(src), "r"(srcsz) : "memory");
}
#define CP_COMMIT() asm volatile("cp.async.commit_group;" ::: "memory")

__device__ __forceinline__ void ldsm4(uint32_t& r0, uint32_t& r1, uint32_t& r2, uint32_t& r3,
                                      uint32_t addr) {
    asm volatile("ldmatrix.sync.aligned.m8n8.x4.shared.b16 {%0,%1,%2,%3}, [%4];"
                 : "=r"(r0), "=r"(r1), "=r"(r2), "=r"(r3) : "r"(addr));
}

#define MMA_BF16(cc, aa, b0v, b1v)                                              \
    asm volatile(                                                               \
        "mma.sync.aligned.m16n8k16.row.col.f32.bf16.bf16.f32 "                  \
        "{%0,%1,%2,%3}, {%4,%5,%6,%7}, {%8,%9}, {%0,%1,%2,%3};"                 \
        : "+f"(cc[0]), "+f"(cc[1]), "+f"(cc[2]), "+f"(cc[3])                    \
        : "r"(aa[0]), "r"(aa[1]), "r"(aa[2]), "r"(aa[3]), "r"(b0v), "r"(b1v))

__device__ __forceinline__ uint32_t pack_bf16x2(float a, float b) {
    __nv_bfloat162 p = __float22bfloat162_rn(make_float2(a, b));
    return *reinterpret_cast<uint32_t*>(&p);
}
__device__ __forceinline__ void split_pair(float v0, float v1, uint32_t& hw, uint32_t& lw) {
    float h0 = __bfloat162float(__float2bfloat16_rn(v0));
    float h1 = __bfloat162float(__float2bfloat16_rn(v1));
    hw = pack_bf16x2(h0, h1);
    lw = pack_bf16x2(v0 - h0, v1 - h1);
}

// ---------------- device: compose+prep+bias tile (bx in 0..3, by in 0..4) ------------
__device__ void compose_tile(int bx, int by, const float* __restrict__ A,
                             const float* __restrict__ B,
                             __nv_bfloat16* __restrict__ hi, __nv_bfloat16* __restrict__ lo,
                             int kpitch, int koff,
                             const float* __restrict__ b2, const float* __restrict__ badd,
                             float* __restrict__ bout)
{
    __shared__ float As[16][64];
    __shared__ float Bs[16][64];
    __shared__ float red[4][64];
    const int t = threadIdx.x;
    if (by == 4) {
        int j = bx * 64 + (t & 63);
        int ks = t >> 6;
        float acc = 0.f;
#pragma unroll 8
        for (int k = ks * 64; k < ks * 64 + 64; k++)
            acc += b2[k] * B[(size_t)k * 256 + j];
        red[ks][t & 63] = acc;
        __syncthreads();
        if (t < 64) {
            int jj = bx * 64 + t;
            bout[jj] = red[0][t] + red[1][t] + red[2][t] + red[3][t] + badd[jj];
        }
        return;
    }

    const int tx = t & 15, ty = t >> 4;
    const int m0 = by * 64, n0 = bx * 64;
    float acc[4][4];
#pragma unroll
    for (int i = 0; i < 4; i++)
#pragma unroll
        for (int j = 0; j < 4; j++) acc[i][j] = 0.f;

    for (int k0 = 0; k0 < 256; k0 += 16) {
#pragma unroll
        for (int i = 0; i < 4; i++) {
            int idx = t + i * 256;
            int r = idx >> 4, c = idx & 15;
            As[c][r] = A[(size_t)(m0 + r) * 256 + k0 + c];
        }
#pragma unroll
        for (int i = 0; i < 4; i++) {
            int idx = t + i * 256;
            int r = idx >> 6, c = idx & 63;
            Bs[r][c] = B[(size_t)(k0 + r) * 256 + n0 + c];
        }
        __syncthreads();
#pragma unroll
        for (int k = 0; k < 16; k++) {
            float ra[4], rb[4];
#pragma unroll
            for (int i = 0; i < 4; i++) ra[i] = As[k][ty * 4 + i];
#pragma unroll
            for (int j = 0; j < 4; j++) rb[j] = Bs[k][tx * 4 + j];
#pragma unroll
            for (int i = 0; i < 4; i++)
#pragma unroll
                for (int j = 0; j < 4; j++) acc[i][j] += ra[i] * rb[j];
        }
        __syncthreads();
    }
#pragma unroll
    for (int i = 0; i < 4; i++) {
        int kk = m0 + ty * 4 + i;
#pragma unroll
        for (int j = 0; j < 4; j++) {
            int nn = n0 + tx * 4 + j;
            float v = acc[i][j];
            __nv_bfloat16 h = __float2bfloat16_rn(v);
            hi[(size_t)nn * kpitch + koff + kk] = h;
            lo[(size_t)nn * kpitch + koff + kk] =
                __float2bfloat16_rn(v - __bfloat162float(h));
        }
    }
}

// ---------------- L1: setup = compose_t | compose_u | prep2(P2) | count --------------
__global__ __launch_bounds__(256) void setup_kernel(
    const float* __restrict__ pre_w2, const float* __restrict__ conv_w,
    const float* __restrict__ post_w1,
    const float* __restrict__ pre_b2, const float* __restrict__ conv_b,
    const float* __restrict__ post_b1,
    __nv_bfloat16* __restrict__ wth, __nv_bfloat16* __restrict__ wtl,
    __nv_bfloat16* __restrict__ wuh, __nv_bfloat16* __restrict__ wul,
    float* __restrict__ cbt, float* __restrict__ cbu,
    const int* __restrict__ dst, int* __restrict__ cnt)
{
    const int bid = blockIdx.x;
    const float* P1 = post_w1;
    const float* P2 = post_w1 + 256 * 256;
    if (bid < 20) {
        compose_tile(bid & 3, bid >> 2, pre_w2, conv_w, wth, wtl, 256, 0,
                     pre_b2, conv_b, cbt);
    } else if (bid < 40) {
        int b = bid - 20;
        compose_tile(b & 3, b >> 2, pre_w2, P1, wuh, wul, 512, 0,
                     pre_b2, post_b1, cbu);
    } else if (bid < 104) {
        // prep2: transpose+split P2 into wuh/wul at koff=256
        __shared__ float tile[32][33];
        int lb = bid - 40;
        int k0 = (lb >> 3) * 32, n0 = (lb & 7) * 32;
        int tx = threadIdx.x & 31, ty = threadIdx.x >> 5;  // 32 x 8
        for (int i = ty; i < 32; i += 8)
            tile[i][tx] = P2[(size_t)(k0 + i) * 256 + n0 + tx];
        __syncthreads();
        for (int i = ty; i < 32; i += 8) {
            float v = tile[tx][i];
            __nv_bfloat16 h = __float2bfloat16_rn(v);
            wuh[(size_t)(n0 + i) * 512 + 256 + k0 + tx] = h;
            wul[(size_t)(n0 + i) * 512 + 256 + k0 + tx] =
                __float2bfloat16_rn(v - __bfloat162float(h));
        }
    } else {
        int e = (bid - 104) * 256 + threadIdx.x;
        if (e < NE) atomicAdd(&cnt[dst[e]], 1);
    }
}

// ---------------- L2: pre (blocks 1..391) | scan (block 0), 1024 threads -------------
__global__ __launch_bounds__(1024) void pre_scan_kernel(
    const float* __restrict__ x, const float* __restrict__ w1, const float* __restrict__ b1,
    __nv_bfloat16* __restrict__ Ch, __nv_bfloat16* __restrict__ Cl,
    const int* __restrict__ cnt, int* __restrict__ rowptr, int* __restrict__ fill)
{
    const int tid = threadIdx.x, lane = tid & 31, warp = tid >> 5;
    if (blockIdx.x == 0) {
        // exclusive scan of cnt -> rowptr, fill
        __shared__ int wsum[32];
        __shared__ int s_carry;
        if (tid == 0) { s_carry = 0; rowptr[0] = 0; }
        __syncthreads();
        for (int base = 0; base < NN; base += 1024) {
            int i = base + tid;
            int v = (i < NN) ? cnt[i] : 0;
            int s = v;
#pragma unroll
            for (int d = 1; d < 32; d <<= 1) {
                int y = __shfl_up_sync(0xffffffffu, s, d);
                if (lane >= d) s += y;
            }
            if (lane == 31) wsum[warp] = s;
            int carry_in = s_carry;
            __syncthreads();
            if (warp == 0) {
                int ws = wsum[lane];
#pragma unroll
                for (int d = 1; d < 32; d <<= 1) {
                    int y = __shfl_up_sync(0xffffffffu, ws, d);
                    if (lane >= d) ws += y;
                }
                wsum[lane] = ws;
            }
            __syncthreads();
            int off = (warp ? wsum[warp - 1] : 0) + carry_in;
            int inc = s + off;
            if (i < NN) {
                rowptr[i + 1] = inc;
                fill[i] = inc - v;
            }
            __syncthreads();
            if (tid == 1023) s_carry = inc;
            __syncthreads();
        }
        return;
    }

    // pre-MLP layer 1: 128 rows per block, 32 warps x 4 rows
    __shared__ float ws[16 * 256];
    __shared__ float bs[256];
    ((float4*)ws)[tid] = ((const float4*)w1)[tid];
    if (tid < 256) bs[tid] = b1[tid];
    __syncthreads();

    const int rb = (blockIdx.x - 1) * 128;
#pragma unroll
    for (int r = 0; r < 4; r++) {
        int row = rb + warp * 4 + r;
        if (row >= NN) break;
        float xv[16];
        const float4* xp = (const float4*)(x + (size_t)row * 16);
#pragma unroll
        for (int q = 0; q < 4; q++) *(float4*)&xv[q * 4] = xp[q];
        float acc[8];
#pragma unroll
        for (int j = 0; j < 8; j++) acc[j] = bs[lane + 32 * j];
#pragma unroll
        for (int k = 0; k < 16; k++) {
            float xk = xv[k];
            const float* wr = &ws[k * 256 + lane];
#pragma unroll
            for (int j = 0; j < 8; j++) acc[j] += xk * wr[32 * j];
        }
#pragma unroll
        for (int j = 0; j < 8; j++) {
            float v = fmaxf(acc[j], 0.f);
            __nv_bfloat16 h = __float2bfloat16_rn(v);
            Ch[(size_t)row * 256 + lane + 32 * j] = h;
            Cl[(size_t)row * 256 + lane + 32 * j] =
                __float2bfloat16_rn(v - __bfloat162float(h));
        }
    }
}

// ---------------- device: tensor-core GEMM body ----------------
template <int ACT>
__device__ void gemm_body(
    int nb, int mb, char* smc,
    const __nv_bfloat16* __restrict__ A1h, const __nv_bfloat16* __restrict__ A1l,
    const __nv_bfloat16* __restrict__ A2h, const __nv_bfloat16* __restrict__ A2l,
    const __nv_bfloat16* __restrict__ Wh,  const __nv_bfloat16* __restrict__ Wl,
    const float* __restrict__ bias,
    __nv_bfloat16* __restrict__ Ch, __nv_bfloat16* __restrict__ Cl,
    int M, int K, int K1)
{
    __shared__ float sbias[128];

    const int tid = threadIdx.x;
    const int wid = tid >> 5, lane = tid & 31;
    const int g = lane >> 2, tg = lane & 3;
    const int wm = wid >> 1, wn = wid & 1;
    const int m0 = mb * 128, n0 = nb * 128;
    const uint32_t smc_u = s2u(smc);

    if (tid < 128) sbias[tid] = bias[n0 + tid];

    const int arow = tid >> 1;
    const int aks  = (tid & 1) * 16;
    const int gm   = m0 + arow;
    const int okA  = (gm < M) ? 16 : 0;

    const int q = lane >> 3, rr = lane & 7;
    const uint32_t aoff0 = (uint32_t)((wm * 32 + (q & 1) * 8 + rr) * 80 + (q >> 1) * 16);
    const uint32_t boff0 = (uint32_t)(20480 + (wn * 64 + (q >> 1) * 8 + rr) * 80 + (q & 1) * 16);

    float acc[2][8][4];
#pragma unroll
    for (int i = 0; i < 2; i++)
#pragma unroll
        for (int j = 0; j < 8; j++)
#pragma unroll
            for (int p = 0; p < 4; p++) acc[i][j][p] = 0.f;

    const int NC = K >> 5;

    auto STAGE = [&](int c) {
        const int ck = c * 32;
        const __nv_bfloat16 *Ah, *Al; int lda, kof;
        if (ck < K1) { Ah = A1h; Al = A1l; lda = K1;     kof = ck; }
        else         { Ah = A2h; Al = A2l; lda = K - K1; kof = ck - K1; }
        const uint32_t sb = smc_u + (uint32_t)((c & 1) * STAGE_B);
        const uint32_t da = sb + (uint32_t)(arow * 80 + (tid & 1) * 32);
        const __nv_bfloat16* pah = Ah + (size_t)gm * lda + kof + aks;
        const __nv_bfloat16* pal = Al + (size_t)gm * lda + kof + aks;
        cp16(da, pah, okA);               cp16(da + 16, pah + 8, okA);
        cp16(da + 10240, pal, okA);       cp16(da + 10240 + 16, pal + 8, okA);
        const __nv_bfloat16* pbh = Wh + (size_t)(n0 + arow) * K + ck + aks;
        const __nv_bfloat16* pbl = Wl + (size_t)(n0 + arow) * K + ck + aks;
        cp16(da + 20480, pbh, 16);        cp16(da + 20480 + 16, pbh + 8, 16);
        cp16(da + 30720, pbl, 16);        cp16(da + 30720 + 16, pbl + 8, 16);
        CP_COMMIT();
    };

    STAGE(0);

    for (int c = 0; c < NC; c++) {
        if (c + 1 < NC) {
            STAGE(c + 1);
            asm volatile("cp.async.wait_group 1;" ::: "memory");
        } else {
            asm volatile("cp.async.wait_group 0;" ::: "memory");
        }
        __syncthreads();

        const uint32_t sb = smc_u + (uint32_t)((c & 1) * STAGE_B);
#pragma unroll
        for (int ks = 0; ks < 2; ks++) {
            const uint32_t ko = (uint32_t)(ks * 32);
            uint32_t ah[2][4], bb[8][2];
            ldsm4(ah[0][0], ah[0][1], ah[0][2], ah[0][3], sb + aoff0 + ko);
            ldsm4(ah[1][0], ah[1][1], ah[1][2], ah[1][3], sb + aoff0 + 1280 + ko);
#pragma unroll
            for (int jp = 0; jp < 4; jp++)
                ldsm4(bb[2 * jp][0], bb[2 * jp][1], bb[2 * jp + 1][0], bb[2 * jp + 1][1],
                      sb + boff0 + (uint32_t)(jp * 1280) + ko);
#pragma unroll
            for (int i = 0; i < 2; i++)
#pragma unroll
                for (int j = 0; j < 8; j++) MMA_BF16(acc[i][j], ah[i], bb[j][0], bb[j][1]);

            uint32_t al[2][4];
            ldsm4(al[0][0], al[0][1], al[0][2], al[0][3], sb + 10240 + aoff0 + ko);
            ldsm4(al[1][0], al[1][1], al[1][2], al[1][3], sb + 10240 + aoff0 + 1280 + ko);
#pragma unroll
            for (int i = 0; i < 2; i++)
#pragma unroll
                for (int j = 0; j < 8; j++) MMA_BF16(acc[i][j], al[i], bb[j][0], bb[j][1]);

#pragma unroll
            for (int jp = 0; jp < 4; jp++)
                ldsm4(bb[2 * jp][0], bb[2 * jp][1], bb[2 * jp + 1][0], bb[2 * jp + 1][1],
                      sb + 10240 + boff0 + (uint32_t)(jp * 1280) + ko);
#pragma unroll
            for (int i = 0; i < 2; i++)
#pragma unroll
                for (int j = 0; j < 8; j++) MMA_BF16(acc[i][j], ah[i], bb[j][0], bb[j][1]);
        }
        __syncthreads();
    }

    // epilogue: bias + activation + hi/lo split store
#pragma unroll
    for (int i = 0; i < 2; i++) {
        int r0 = m0 + wm * 32 + i * 16 + g;
#pragma unroll
        for (int j = 0; j < 8; j++) {
            int cl = wn * 64 + j * 8 + tg * 2;
            float b0 = sbias[cl], b1 = sbias[cl + 1];
            float v0 = acc[i][j][0] + b0, v1 = acc[i][j][1] + b1;
            float v2 = acc[i][j][2] + b0, v3 = acc[i][j][3] + b1;
            if (ACT == 1) {
                v0 = fmaxf(v0, 0.f); v1 = fmaxf(v1, 0.f);
                v2 = fmaxf(v2, 0.f); v3 = fmaxf(v3, 0.f);
            }
            uint32_t hw, lw;
            if (r0 < M) {
                split_pair(v0, v1, hw, lw);
                *(uint32_t*)(Ch + (size_t)r0 * 256 + n0 + cl) = hw;
                *(uint32_t*)(Cl + (size_t)r0 * 256 + n0 + cl) = lw;
            }
            if (r0 + 8 < M) {
                split_pair(v2, v3, hw, lw);
                *(uint32_t*)(Ch + (size_t)(r0 + 8) * 256 + n0 + cl) = hw;
                *(uint32_t*)(Cl + (size_t)(r0 + 8) * 256 + n0 + cl) = lw;
            }
        }
    }
}

#define GEMM_BLKS 782  // 2 x 391

// ---------------- L3: t-GEMM (blocks 0..781) | scatter (rest) ------------------------
__global__ __launch_bounds__(256, 2) void gemm_scatter_kernel(
    const __nv_bfloat16* __restrict__ ah, const __nv_bfloat16* __restrict__ al,
    const __nv_bfloat16* __restrict__ wth, const __nv_bfloat16* __restrict__ wtl,
    const float* __restrict__ cbt,
    __nv_bfloat16* __restrict__ th, __nv_bfloat16* __restrict__ tl,
    const int* __restrict__ src, const int* __restrict__ dst,
    int* __restrict__ fill, int* __restrict__ col)
{
    extern __shared__ char smc[];
    const int bid = blockIdx.x;
    if (bid < GEMM_BLKS) {
        gemm_body<1>(bid & 1, bid >> 1, smc, ah, al, nullptr, nullptr,
                     wth, wtl, cbt, th, tl, NN, 256, 256);
    } else {
        int e = (bid - GEMM_BLKS) * 256 + threadIdx.x;
        if (e < NE) {
            int slot = atomicAdd(&fill[dst[e]], 1);
            col[slot] = src[e];
        }
    }
}

// ---------------- L5: u-GEMM ----------------
__global__ __launch_bounds__(256, 2) void ugemm_kernel(
    const __nv_bfloat16* __restrict__ ah, const __nv_bfloat16* __restrict__ al,
    const __nv_bfloat16* __restrict__ gh, const __nv_bfloat16* __restrict__ gl,
    const __nv_bfloat16* __restrict__ wuh, const __nv_bfloat16* __restrict__ wul,
    const float* __restrict__ cbu,
    __nv_bfloat16* __restrict__ uh, __nv_bfloat16* __restrict__ ul)
{
    extern __shared__ char smc[];
    const int bid = blockIdx.x;
    gemm_body<1>(bid & 1, bid >> 1, smc, ah, al, gh, gl,
                 wuh, wul, cbu, uh, ul, NN, 512, 256);
}

// ---------------- L4: atomic-free aggregation (4 nodes/block, 1 warp each) -----------
__device__ __forceinline__ void acc8(float* acc, uint4 hv, uint4 lv) {
    const uint32_t* h = (const uint32_t*)&hv;
    const uint32_t* l = (const uint32_t*)&lv;
#pragma unroll
    for (int p = 0; p < 4; p++) {
        __nv_bfloat162 h2 = *reinterpret_cast<const __nv_bfloat162*>(&h[p]);
        __nv_bfloat162 l2 = *reinterpret_cast<const __nv_bfloat162*>(&l[p]);
        acc[2 * p]     += __low2float(h2)  + __low2float(l2);
        acc[2 * p + 1] += __high2float(h2) + __high2float(l2);
    }
}

__global__ __launch_bounds__(128) void agg_kernel(
    const __nv_bfloat16* __restrict__ th, const __nv_bfloat16* __restrict__ tl,
    const int* __restrict__ rowptr, const int* __restrict__ col,
    __nv_bfloat16* __restrict__ aggh, __nv_bfloat16* __restrict__ aggl)
{
    const int node = blockIdx.x * 4 + (threadIdx.x >> 5);
    if (node >= NN) return;
    const int tid = threadIdx.x & 31;
    const int s = rowptr[node];
    const int e = rowptr[node + 1];
    float acc[8];
#pragma unroll
    for (int p = 0; p < 8; p++) acc[p] = 0.f;

    int i = s;
    for (; i + 4 <= e; i += 4) {
        int c0 = __ldg(&col[i]),     c1 = __ldg(&col[i + 1]);
        int c2 = __ldg(&col[i + 2]), c3 = __ldg(&col[i + 3]);
        uint4 h0 = *(const uint4*)(th + (size_t)c0 * HID + tid * 8);
        uint4 l0 = *(const uint4*)(tl + (size_t)c0 * HID + tid * 8);
        uint4 h1 = *(const uint4*)(th + (size_t)c1 * HID + tid * 8);
        uint4 l1 = *(const uint4*)(tl + (size_t)c1 * HID + tid * 8);
        uint4 h2 = *(const uint4*)(th + (size_t)c2 * HID + tid * 8);
        uint4 l2 = *(const uint4*)(tl + (size_t)c2 * HID + tid * 8);
        uint4 h3 = *(const uint4*)(th + (size_t)c3 * HID + tid * 8);
        uint4 l3 = *(const uint4*)(tl + (size_t)c3 * HID + tid * 8);
        acc8(acc, h0, l0); acc8(acc, h1, l1);
        acc8(acc, h2, l2); acc8(acc, h3, l3);
    }
    for (; i < e; i++) {
        int c0 = __ldg(&col[i]);
        uint4 h0 = *(const uint4*)(th + (size_t)c0 * HID + tid * 8);
        uint4 l0 = *(const uint4*)(tl + (size_t)c0 * HID + tid * 8);
        acc8(acc, h0, l0);
    }

    uint32_t hw[4], lw[4];
#pragma unroll
    for (int p = 0; p < 4; p++) split_pair(acc[2 * p], acc[2 * p + 1], hw[p], lw[p]);
    *(uint4*)(aggh + (size_t)node * HID + tid * 8) = *(uint4*)hw;
    *(uint4*)(aggl + (size_t)node * HID + tid * 8) = *(uint4*)lw;
}

// ---------------- L6: output projection ----------------
__global__ __launch_bounds__(256) void out_kernel(
    const __nv_bfloat16* __restrict__ uh, const __nv_bfloat16* __restrict__ ul,
    const float* __restrict__ w, const float* __restrict__ b,
    float* __restrict__ out, int M)
{
    __shared__ float ws[256 * 16];
    __shared__ float bs[16];
    const int tid = threadIdx.x;
    for (int i = tid; i < 256 * 16 / 4; i += 256)
        ((float4*)ws)[i] = ((const float4*)w)[i];
    if (tid < 16) bs[tid] = b[tid];
    __syncthreads();

    const int mloc = tid >> 1;
    const int off  = (tid & 1) * 8;
    const int m = blockIdx.x * 128 + mloc;
    if (m >= M) return;

    float acc[8];
#pragma unroll
    for (int j = 0; j < 8; j++) acc[j] = bs[off + j];

    const uint4* ph = (const uint4*)(uh + (size_t)m * HID);
    const uint4* pl = (const uint4*)(ul + (size_t)m * HID);
#pragma unroll 4
    for (int kc = 0; kc < 32; kc++) {
        uint4 hv = ph[kc], lv = pl[kc];
        const uint32_t* hp = (const uint32_t*)&hv;
        const uint32_t* lp = (const uint32_t*)&lv;
        float f[8];
#pragma unroll
        for (int p = 0; p < 4; p++) {
            __nv_bfloat162 h2 = *reinterpret_cast<const __nv_bfloat162*>(&hp[p]);
            __nv_bfloat162 l2 = *reinterpret_cast<const __nv_bfloat162*>(&lp[p]);
            f[2 * p]     = __low2float(h2)  + __low2float(l2);
            f[2 * p + 1] = __high2float(h2) + __high2float(l2);
        }
#pragma unroll
        for (int qv = 0; qv < 8; qv++) {
            const float* wr = &ws[(kc * 8 + qv) * 16 + off];
#pragma unroll
            for (int j = 0; j < 8; j++) acc[j] += f[qv] * wr[j];
        }
    }
    float o[8];
#pragma unroll
    for (int j = 0; j < 8; j++) o[j] = tanhf(acc[j]);
    float* op = out + (size_t)m * 16 + off;
    *(float4*)(op)     = *(float4*)&o[0];
    *(float4*)(op + 4) = *(float4*)&o[4];
}

// ---------------- launcher ----------------
extern "C" void kernel_launch(void* const* d_in, const int* in_sizes, int n_in,
                              void* d_out, int out_size) {
    const float* x       = (const float*)d_in[0];
    const int*   ei      = (const int*)d_in[1];
    const float* pre_w1  = (const float*)d_in[2];
    const float* pre_b1  = (const float*)d_in[3];
    const float* pre_w2  = (const float*)d_in[4];
    const float* pre_b2  = (const float*)d_in[5];
    const float* conv_w  = (const float*)d_in[6];
    const float* conv_b  = (const float*)d_in[7];
    const float* post_w1 = (const float*)d_in[8];
    const float* post_b1 = (const float*)d_in[9];
    const float* post_w2 = (const float*)d_in[10];
    const float* post_b2 = (const float*)d_in[11];
    float* out = (float*)d_out;

    const int* src = ei;
    const int* dst = ei + NE;

    __nv_bfloat16 *ah, *al, *th, *tl, *gh, *gl, *uh, *ul;
    int *cnt, *rowptr, *fill, *col;
    float *cbt, *cbu;
    __nv_bfloat16 *wth, *wtl, *wuh, *wul;
    cudaGetSymbolAddress((void**)&ah, g_ah);   cudaGetSymbolAddress((void**)&al, g_al);
    cudaGetSymbolAddress((void**)&th, g_th);   cudaGetSymbolAddress((void**)&tl, g_tl);
    cudaGetSymbolAddress((void**)&gh, g_gh);   cudaGetSymbolAddress((void**)&gl, g_gl);
    cudaGetSymbolAddress((void**)&uh, g_uh);   cudaGetSymbolAddress((void**)&ul, g_ul);
    cudaGetSymbolAddress((void**)&cnt, g_cnt);
    cudaGetSymbolAddress((void**)&rowptr, g_rowptr);
    cudaGetSymbolAddress((void**)&fill, g_fill);
    cudaGetSymbolAddress((void**)&col, g_col);
    cudaGetSymbolAddress((void**)&cbt, g_cbt); cudaGetSymbolAddress((void**)&cbu, g_cbu);
    cudaGetSymbolAddress((void**)&wth, g_wth); cudaGetSymbolAddress((void**)&wtl, g_wtl);
    cudaGetSymbolAddress((void**)&wuh, g_wuh); cudaGetSymbolAddress((void**)&wul, g_wul);

    const int DSMEM = 2 * STAGE_B;  // 80 KB
    cudaFuncSetAttribute(gemm_scatter_kernel, cudaFuncAttributeMaxDynamicSharedMemorySize, DSMEM);
    cudaFuncSetAttribute(ugemm_kernel, cudaFuncAttributeMaxDynamicSharedMemorySize, DSMEM);

    cudaMemsetAsync(cnt, 0, NN * sizeof(int), 0);

    // L1: compose_t(20) | compose_u(20) | prep2(64) | count(3125)
    setup_kernel<<<104 + 3125, 256>>>(pre_w2, conv_w, post_w1, pre_b2, conv_b, post_b1,
                                      wth, wtl, wuh, wul, cbt, cbu, dst, cnt);
    // L2: scan(1) | pre-MLP(391)
    pre_scan_kernel<<<392, 1024>>>(x, pre_w1, pre_b1, ah, al, cnt, rowptr, fill);
    // L3: t-GEMM(782) | scatter(3125)
    gemm_scatter_kernel<<<GEMM_BLKS + 3125, 256, DSMEM>>>(ah, al, wth, wtl, cbt,
                                                          th, tl, src, dst, fill, col);
    // L4: aggregation
    agg_kernel<<<(NN + 3) / 4, 128>>>(th, tl, rowptr, col, gh, gl);
    // L5: u = relu(a@Wp + agg@P2 + bu)
    ugemm_kernel<<<GEMM_BLKS, 256, DSMEM>>>(ah, al, gh, gl, wuh, wul, cbu, uh, ul);
    // L6: out = tanh(u@post_w2 + post_b2)
    out_kernel<<<(NN + 127) / 128, 256>>>(uh, ul, post_w2, post_b2, out, NN);
}